// round 1
// baseline (speedup 1.0000x reference)
#include <cuda_runtime.h>
#include <math.h>
#include <stdint.h>

// ---------------------------------------------------------------------------
// ImbalancedGAT: 2-layer GAT (PyG GATConv semantics) on GB300.
//   N=50000 nodes, E=1.6M edges (+N self loops), IN=128, L1: 2 heads x 64,
//   L2: 1 head x 2.
// Strategy:
//   1. sniff edge dtype (int32 vs int64), convert to int32 src/dst.
//   2. GEMM1 (block per node) fused with per-node attention halves.
//   3. edge pass: atomic float max of leaky-relu logits per (dst, head).
//   4. edge pass: w = exp(logit - m[dst]); accumulate w and w*xw[src]
//      (un-normalized) via red.global.add.v4.f32 -> removes a 3rd edge pass.
//   5. node pass: normalize + bias + ELU (in place) -> h.
//   6. warp-per-node GEMM2 + attention halves; repeat edge passes (2 ch).
//   7. normalize -> d_out.
// ---------------------------------------------------------------------------

#define NMAX 50000
#define EMAX 1600000
#define FULL 0xffffffffu

// scratch (static __device__ arrays; no allocation allowed)
__device__ int   g_src[EMAX];
__device__ int   g_dst[EMAX];
__device__ float g_xw1[NMAX * 128];
__device__ float g_acc1[NMAX * 128];
__device__ float g_as1[NMAX * 2];
__device__ float g_ad1[NMAX * 2];
__device__ float g_m1[NMAX * 2];
__device__ float g_den1[NMAX * 2];
__device__ float g_xw2[NMAX * 2];
__device__ float g_as2[NMAX];
__device__ float g_ad2[NMAX];
__device__ float g_m2[NMAX];
__device__ float g_den2[NMAX];
__device__ float g_acc2[NMAX * 2];
__device__ int   g_is64[1];

__device__ __forceinline__ float lrelu(float x) { return x > 0.0f ? x : 0.2f * x; }

__device__ __forceinline__ void atomicMaxF(float* addr, float v) {
    if (v >= 0.0f) atomicMax((int*)addr, __float_as_int(v));
    else           atomicMin((unsigned int*)addr, __float_as_uint(v));
}

__device__ __forceinline__ void red_add_v4(float* addr, float a, float b, float c, float d) {
    asm volatile("red.global.add.v4.f32 [%0], {%1,%2,%3,%4};"
                 :: "l"(__cvta_generic_to_global(addr)),
                    "f"(a), "f"(b), "f"(c), "f"(d)
                 : "memory");
}

// --- dtype sniff: int64 edge data has zero high words (indices < 2^31) ------
__global__ void sniff_kernel(const int* e) {
    __shared__ int any;
    if (threadIdx.x == 0) any = 0;
    __syncthreads();
    if (e[2 * threadIdx.x + 1] != 0) atomicOr(&any, 1);
    __syncthreads();
    if (threadIdx.x == 0) g_is64[0] = (any == 0) ? 1 : 0;
}

__global__ void convert_edges(const void* eraw, int E) {
    int i = blockIdx.x * blockDim.x + threadIdx.x;
    if (i >= E) return;
    if (g_is64[0]) {
        const long long* e = (const long long*)eraw;
        g_src[i] = (int)e[i];
        g_dst[i] = (int)e[(size_t)E + i];
    } else {
        const int* e = (const int*)eraw;
        g_src[i] = e[i];
        g_dst[i] = e[E + i];
    }
}

__global__ void fill_f(float* p, int n, float v) {
    int i = blockIdx.x * blockDim.x + threadIdx.x;
    int stride = gridDim.x * blockDim.x;
    for (; i < n; i += stride) p[i] = v;
}

// --- layer 1 GEMM + attention halves (block = one node, 128 threads) -------
__global__ void gemm1_kernel(const float* __restrict__ x,
                             const float* __restrict__ W1,
                             const float* __restrict__ a_src1,
                             const float* __restrict__ a_dst1) {
    int n = blockIdx.x;
    int t = threadIdx.x;
    __shared__ float xr[128];
    __shared__ float r1[128];
    __shared__ float r2[128];
    xr[t] = x[n * 128 + t];
    __syncthreads();
    float acc = 0.0f;
#pragma unroll 16
    for (int k = 0; k < 128; k++) acc += xr[k] * W1[k * 128 + t];
    g_xw1[n * 128 + t] = acc;
    r1[t] = acc * a_src1[t];   // a_src1 flattened [2,64] matches col = h*64+c
    r2[t] = acc * a_dst1[t];
    __syncthreads();
    for (int o = 32; o >= 1; o >>= 1) {
        if ((t & 63) < o) { r1[t] += r1[t + o]; r2[t] += r2[t + o]; }
        __syncthreads();
    }
    if (t == 0)  { g_as1[2 * n]     = r1[0];  g_ad1[2 * n]     = r2[0];  }
    if (t == 64) { g_as1[2 * n + 1] = r1[64]; g_ad1[2 * n + 1] = r2[64]; }
}

// --- layer 1 edge max (thread per edge, both heads) -------------------------
__global__ void edge_max1(int E, int N) {
    int i = blockIdx.x * blockDim.x + threadIdx.x;
    int T = E + N;
    if (i >= T) return;
    int s, d;
    if (i < E) { s = g_src[i]; d = g_dst[i]; } else { s = d = i - E; }
    float2 as = *(const float2*)&g_as1[2 * s];
    float2 ad = *(const float2*)&g_ad1[2 * d];
    atomicMaxF(&g_m1[2 * d],     lrelu(as.x + ad.x));
    atomicMaxF(&g_m1[2 * d + 1], lrelu(as.y + ad.y));
}

// --- layer 1 edge aggregate (warp per edge, 128 channels) -------------------
__global__ void edge_agg1(int E, int N) {
    int gtid = blockIdx.x * blockDim.x + threadIdx.x;
    int w = gtid >> 5;
    int lane = gtid & 31;
    int T = E + N;
    if (w >= T) return;
    int s, d;
    if (w < E) { s = g_src[w]; d = g_dst[w]; } else { s = d = w - E; }
    float2 as = *(const float2*)&g_as1[2 * s];
    float2 ad = *(const float2*)&g_ad1[2 * d];
    float2 m  = *(const float2*)&g_m1[2 * d];
    float w0 = expf(lrelu(as.x + ad.x) - m.x);
    float w1 = expf(lrelu(as.y + ad.y) - m.y);
    if (lane == 0) {
        atomicAdd(&g_den1[2 * d],     w0);
        atomicAdd(&g_den1[2 * d + 1], w1);
    }
    float ww = (lane < 16) ? w0 : w1;          // head = channel/64, lane*4 channels
    float4 xv = *(const float4*)&g_xw1[s * 128 + lane * 4];
    red_add_v4(&g_acc1[d * 128 + lane * 4], xv.x * ww, xv.y * ww, xv.z * ww, xv.w * ww);
}

// --- layer 1 normalize + bias + ELU (in place -> h) -------------------------
__global__ void norm1_elu(const float* __restrict__ b1, int N) {
    int idx = blockIdx.x * blockDim.x + threadIdx.x;
    if (idx >= N * 128) return;
    int n = idx >> 7;
    int c = idx & 127;
    int h = c >> 6;
    float v = g_acc1[idx] / (g_den1[2 * n + h] + 1e-16f) + b1[c];
    g_acc1[idx] = (v > 0.0f) ? v : expm1f(v);
}

// --- layer 2 GEMM + attention halves (warp per node) ------------------------
__global__ void gemm2_kernel(const float* __restrict__ W2,
                             const float* __restrict__ a_src2,
                             const float* __restrict__ a_dst2, int N) {
    int gtid = blockIdx.x * blockDim.x + threadIdx.x;
    int n = gtid >> 5;
    int lane = gtid & 31;
    if (n >= N) return;
    float s0 = 0.0f, s1 = 0.0f;
#pragma unroll
    for (int j = 0; j < 4; j++) {
        int k = lane + 32 * j;
        float hv = g_acc1[n * 128 + k];
        s0 += hv * W2[2 * k];
        s1 += hv * W2[2 * k + 1];
    }
#pragma unroll
    for (int o = 16; o >= 1; o >>= 1) {
        s0 += __shfl_down_sync(FULL, s0, o);
        s1 += __shfl_down_sync(FULL, s1, o);
    }
    if (lane == 0) {
        g_xw2[2 * n]     = s0;
        g_xw2[2 * n + 1] = s1;
        g_as2[n] = s0 * a_src2[0] + s1 * a_src2[1];
        g_ad2[n] = s0 * a_dst2[0] + s1 * a_dst2[1];
    }
}

// --- layer 2 edge passes ----------------------------------------------------
__global__ void edge_max2(int E, int N) {
    int i = blockIdx.x * blockDim.x + threadIdx.x;
    int T = E + N;
    if (i >= T) return;
    int s, d;
    if (i < E) { s = g_src[i]; d = g_dst[i]; } else { s = d = i - E; }
    atomicMaxF(&g_m2[d], lrelu(g_as2[s] + g_ad2[d]));
}

__global__ void edge_agg2(int E, int N) {
    int i = blockIdx.x * blockDim.x + threadIdx.x;
    int T = E + N;
    if (i >= T) return;
    int s, d;
    if (i < E) { s = g_src[i]; d = g_dst[i]; } else { s = d = i - E; }
    float w = expf(lrelu(g_as2[s] + g_ad2[d]) - g_m2[d]);
    float2 xv = *(const float2*)&g_xw2[2 * s];
    atomicAdd(&g_den2[d], w);
    atomicAdd(&g_acc2[2 * d],     w * xv.x);
    atomicAdd(&g_acc2[2 * d + 1], w * xv.y);
}

__global__ void norm2_out(float* __restrict__ out, const float* __restrict__ b2, int N) {
    int idx = blockIdx.x * blockDim.x + threadIdx.x;
    if (idx >= 2 * N) return;
    out[idx] = g_acc2[idx] / (g_den2[idx >> 1] + 1e-16f) + b2[idx & 1];
}

// ---------------------------------------------------------------------------

extern "C" void kernel_launch(void* const* d_in, const int* in_sizes, int n_in,
                              void* d_out, int out_size) {
    const float* x      = (const float*)d_in[0];
    const void*  edges  = d_in[1];
    const float* W1     = (const float*)d_in[2];
    const float* a_src1 = (const float*)d_in[3];
    const float* a_dst1 = (const float*)d_in[4];
    const float* b1     = (const float*)d_in[5];
    const float* W2     = (const float*)d_in[6];
    const float* a_src2 = (const float*)d_in[7];
    const float* a_dst2 = (const float*)d_in[8];
    const float* b2     = (const float*)d_in[9];

    int N = in_sizes[0] / 128;     // 50000
    int E = in_sizes[1] / 2;       // 1600000 (element count identical for i32/i64)
    int T = E + N;

    // pointers to __device__ globals for the fill kernels
    float *p_m1, *p_den1, *p_acc1, *p_m2, *p_den2, *p_acc2;
    cudaGetSymbolAddress((void**)&p_m1,   g_m1);
    cudaGetSymbolAddress((void**)&p_den1, g_den1);
    cudaGetSymbolAddress((void**)&p_acc1, g_acc1);
    cudaGetSymbolAddress((void**)&p_m2,   g_m2);
    cudaGetSymbolAddress((void**)&p_den2, g_den2);
    cudaGetSymbolAddress((void**)&p_acc2, g_acc2);

    sniff_kernel<<<1, 256>>>((const int*)edges);
    convert_edges<<<(E + 255) / 256, 256>>>(edges, E);

    fill_f<<<1024, 256>>>(p_m1,   2 * N,   -INFINITY);
    fill_f<<<1024, 256>>>(p_den1, 2 * N,   0.0f);
    fill_f<<<4096, 256>>>(p_acc1, 128 * N, 0.0f);
    fill_f<<<1024, 256>>>(p_m2,   N,       -INFINITY);
    fill_f<<<1024, 256>>>(p_den2, N,       0.0f);
    fill_f<<<1024, 256>>>(p_acc2, 2 * N,   0.0f);

    gemm1_kernel<<<N, 128>>>(x, W1, a_src1, a_dst1);
    edge_max1<<<(T + 255) / 256, 256>>>(E, N);
    {
        long long threads = (long long)T * 32;
        edge_agg1<<<(int)((threads + 255) / 256), 256>>>(E, N);
    }
    norm1_elu<<<(N * 128 + 255) / 256, 256>>>(b1, N);

    gemm2_kernel<<<(N * 32 + 255) / 256, 256>>>(W2, a_src2, a_dst2, N);
    edge_max2<<<(T + 255) / 256, 256>>>(E, N);
    edge_agg2<<<(T + 255) / 256, 256>>>(E, N);
    norm2_out<<<(2 * N + 255) / 256, 256>>>((float*)d_out, b2, N);
}

// round 3
// speedup vs baseline: 1.7938x; 1.7938x over previous
#include <cuda_runtime.h>
#include <math.h>
#include <stdint.h>

// ---------------------------------------------------------------------------
// ImbalancedGAT round 2 (resubmit; broker timeout last round): CSR restructure.
//   - convert edges (+histogram via red) -> scan -> counting-sort scatter
//   - gemm1: 8 nodes/block (W1 L1 reuse), fused attention halves
//   - agg1: warp-per-dst over CSR: max, softmax, 128-ch aggregate in regs,
//           fused normalize+bias+ELU+GEMM2+attention halves (h never stored)
//   - agg2: warp-per-dst over CSR, writes d_out directly
// No large atomics except CSR build. No m/den/acc arrays.
// ---------------------------------------------------------------------------

#define NMAX 50000
#define EMAX 1600000
#define FULL 0xffffffffu

__device__ int   g_src[EMAX];
__device__ int   g_dst[EMAX];
__device__ int   g_ssrc[EMAX + NMAX];   // CSR column indices (src per dst-sorted edge)
__device__ int   g_count[NMAX];
__device__ int   g_off[NMAX + 1];
__device__ int   g_cursor[NMAX];
__device__ float g_xw1[NMAX * 128];
__device__ float g_as1[NMAX * 2];
__device__ float g_ad1[NMAX * 2];
__device__ float g_xw2[NMAX * 2];
__device__ float g_as2[NMAX];
__device__ float g_ad2[NMAX];
__device__ int   g_is64[1];

__device__ __forceinline__ float lrelu(float x) { return x > 0.0f ? x : 0.2f * x; }

// --- dtype sniff ------------------------------------------------------------
__global__ void sniff_kernel(const int* e) {
    __shared__ int any;
    if (threadIdx.x == 0) any = 0;
    __syncthreads();
    if (e[2 * threadIdx.x + 1] != 0) atomicOr(&any, 1);
    __syncthreads();
    if (threadIdx.x == 0) g_is64[0] = (any == 0) ? 1 : 0;
}

__global__ void fill_count(int N) {
    int i = blockIdx.x * blockDim.x + threadIdx.x;
    if (i < N) g_count[i] = 1;   // self loop
}

// --- convert + histogram ----------------------------------------------------
__global__ void convert_hist(const void* eraw, int E) {
    int i = blockIdx.x * blockDim.x + threadIdx.x;
    if (i >= E) return;
    int s, d;
    if (g_is64[0]) {
        const long long* e = (const long long*)eraw;
        s = (int)e[i];
        d = (int)e[(size_t)E + i];
    } else {
        const int* e = (const int*)eraw;
        s = e[i];
        d = e[E + i];
    }
    g_src[i] = s;
    g_dst[i] = d;
    atomicAdd(&g_count[d], 1);
}

// --- single-block scan (N=50000) -------------------------------------------
__global__ void scan_kernel(int N) {
    __shared__ int sh[1024];
    int tid = threadIdx.x;
    int chunk = (N + 1023) / 1024;
    int start = tid * chunk;
    int sum = 0;
    for (int j = 0; j < chunk; j++) {
        int idx = start + j;
        if (idx < N) sum += g_count[idx];
    }
    sh[tid] = sum;
    __syncthreads();
    for (int off = 1; off < 1024; off <<= 1) {
        int v = (tid >= off) ? sh[tid - off] : 0;
        __syncthreads();
        sh[tid] += v;
        __syncthreads();
    }
    int run = (tid > 0) ? sh[tid - 1] : 0;
    for (int j = 0; j < chunk; j++) {
        int idx = start + j;
        if (idx < N) {
            g_off[idx] = run;
            g_cursor[idx] = run;
            run += g_count[idx];
        }
    }
    if (tid == 1023) g_off[N] = sh[1023];
}

// --- counting-sort scatter (edges + self loops) -----------------------------
__global__ void scatter_kernel(int E, int N) {
    int i = blockIdx.x * blockDim.x + threadIdx.x;
    if (i >= E + N) return;
    int s, d;
    if (i < E) { s = g_src[i]; d = g_dst[i]; }
    else       { s = d = i - E; }
    int pos = atomicAdd(&g_cursor[d], 1);
    g_ssrc[pos] = s;
}

// --- layer 1 GEMM: 8 nodes per block, 128 threads ---------------------------
__global__ void gemm1_kernel(const float* __restrict__ x,
                             const float* __restrict__ W1,
                             const float* __restrict__ a_src1,
                             const float* __restrict__ a_dst1, int N) {
    int nb = blockIdx.x * 8;
    int t = threadIdx.x;
    int lane = t & 31;
    int wid = t >> 5;
    __shared__ float xs[8][128];
    __shared__ float ps[8][4], pd[8][4];
#pragma unroll
    for (int r = 0; r < 8; r++)
        xs[r][t] = x[(nb + r) * 128 + t];
    float a_s = a_src1[t];
    float a_d = a_dst1[t];
    __syncthreads();
    float acc[8] = {0, 0, 0, 0, 0, 0, 0, 0};
    for (int k = 0; k < 128; k += 4) {
        float w0 = W1[(k + 0) * 128 + t];
        float w1 = W1[(k + 1) * 128 + t];
        float w2 = W1[(k + 2) * 128 + t];
        float w3 = W1[(k + 3) * 128 + t];
#pragma unroll
        for (int r = 0; r < 8; r++) {
            float4 xv = *(const float4*)&xs[r][k];
            acc[r] += xv.x * w0 + xv.y * w1 + xv.z * w2 + xv.w * w3;
        }
    }
#pragma unroll
    for (int r = 0; r < 8; r++) {
        g_xw1[(nb + r) * 128 + t] = acc[r];
        float v1 = acc[r] * a_s;
        float v2 = acc[r] * a_d;
#pragma unroll
        for (int o = 16; o >= 1; o >>= 1) {
            v1 += __shfl_down_sync(FULL, v1, o);
            v2 += __shfl_down_sync(FULL, v2, o);
        }
        if (lane == 0) { ps[r][wid] = v1; pd[r][wid] = v2; }
    }
    __syncthreads();
    if (t < 8) {
        int n = nb + t;
        g_as1[2 * n]     = ps[t][0] + ps[t][1];
        g_as1[2 * n + 1] = ps[t][2] + ps[t][3];
        g_ad1[2 * n]     = pd[t][0] + pd[t][1];
        g_ad1[2 * n + 1] = pd[t][2] + pd[t][3];
    }
}

// --- layer 1 aggregate: warp per dst node, fused everything -----------------
__global__ void agg1_kernel(const float* __restrict__ b1,
                            const float* __restrict__ W2,
                            const float* __restrict__ a_src2,
                            const float* __restrict__ a_dst2, int N) {
    int gw = (blockIdx.x * blockDim.x + threadIdx.x) >> 5;
    int lane = threadIdx.x & 31;
    if (gw >= N) return;
    int d = gw;
    int o = g_off[d];
    int deg = g_off[d + 1] - o;
    float ad0 = g_ad1[2 * d];
    float ad1 = g_ad1[2 * d + 1];

    // phase 1: per-head max logit
    float m0 = -INFINITY, m1 = -INFINITY;
    for (int i = lane; i < deg; i += 32) {
        int s = g_ssrc[o + i];
        float2 as = *(const float2*)&g_as1[2 * s];
        m0 = fmaxf(m0, lrelu(as.x + ad0));
        m1 = fmaxf(m1, lrelu(as.y + ad1));
    }
#pragma unroll
    for (int off = 16; off >= 1; off >>= 1) {
        m0 = fmaxf(m0, __shfl_xor_sync(FULL, m0, off));
        m1 = fmaxf(m1, __shfl_xor_sync(FULL, m1, off));
    }

    // phase 2: weighted aggregation; lane owns channels [4*lane, 4*lane+4)
    int head = lane >> 4;                  // channel / 64
    float acc0 = 0, acc1 = 0, acc2 = 0, acc3 = 0;
    float den0 = 0, den1 = 0;
    int base = 0;
    for (; base + 32 <= deg; base += 32) {
        int s = g_ssrc[o + base + lane];
        float2 as = *(const float2*)&g_as1[2 * s];
        float w0 = expf(lrelu(as.x + ad0) - m0);
        float w1 = expf(lrelu(as.y + ad1) - m1);
        den0 += w0;
        den1 += w1;
#pragma unroll 8
        for (int j = 0; j < 32; j++) {
            int sj = __shfl_sync(FULL, s, j);
            float wa = __shfl_sync(FULL, w0, j);
            float wb = __shfl_sync(FULL, w1, j);
            float wj = head ? wb : wa;
            float4 xv = *(const float4*)&g_xw1[sj * 128 + lane * 4];
            acc0 += wj * xv.x;
            acc1 += wj * xv.y;
            acc2 += wj * xv.z;
            acc3 += wj * xv.w;
        }
    }
    int rem = deg - base;
    if (rem > 0) {
        int s = 0;
        float w0 = 0, w1 = 0;
        if (lane < rem) {
            s = g_ssrc[o + base + lane];
            float2 as = *(const float2*)&g_as1[2 * s];
            w0 = expf(lrelu(as.x + ad0) - m0);
            w1 = expf(lrelu(as.y + ad1) - m1);
            den0 += w0;
            den1 += w1;
        }
        for (int j = 0; j < rem; j++) {
            int sj = __shfl_sync(FULL, s, j);
            float wa = __shfl_sync(FULL, w0, j);
            float wb = __shfl_sync(FULL, w1, j);
            float wj = head ? wb : wa;
            float4 xv = *(const float4*)&g_xw1[sj * 128 + lane * 4];
            acc0 += wj * xv.x;
            acc1 += wj * xv.y;
            acc2 += wj * xv.z;
            acc3 += wj * xv.w;
        }
    }
    // reduce denominators across warp
#pragma unroll
    for (int off = 16; off >= 1; off >>= 1) {
        den0 += __shfl_xor_sync(FULL, den0, off);
        den1 += __shfl_xor_sync(FULL, den1, off);
    }
    float inv = 1.0f / ((head ? den1 : den0) + 1e-16f);

    // normalize + bias + ELU (h, never stored) then GEMM2 + attention halves
    int c = lane * 4;
    float h0 = acc0 * inv + b1[c + 0];
    float h1 = acc1 * inv + b1[c + 1];
    float h2 = acc2 * inv + b1[c + 2];
    float h3 = acc3 * inv + b1[c + 3];
    h0 = h0 > 0.0f ? h0 : expm1f(h0);
    h1 = h1 > 0.0f ? h1 : expm1f(h1);
    h2 = h2 > 0.0f ? h2 : expm1f(h2);
    h3 = h3 > 0.0f ? h3 : expm1f(h3);

    float s0 = h0 * W2[2 * c + 0] + h1 * W2[2 * c + 2] + h2 * W2[2 * c + 4] + h3 * W2[2 * c + 6];
    float s1 = h0 * W2[2 * c + 1] + h1 * W2[2 * c + 3] + h2 * W2[2 * c + 5] + h3 * W2[2 * c + 7];
#pragma unroll
    for (int off = 16; off >= 1; off >>= 1) {
        s0 += __shfl_xor_sync(FULL, s0, off);
        s1 += __shfl_xor_sync(FULL, s1, off);
    }
    if (lane == 0) {
        g_xw2[2 * d]     = s0;
        g_xw2[2 * d + 1] = s1;
        g_as2[d] = s0 * a_src2[0] + s1 * a_src2[1];
        g_ad2[d] = s0 * a_dst2[0] + s1 * a_dst2[1];
    }
}

// --- layer 2 aggregate: warp per dst node, writes output --------------------
__global__ void agg2_kernel(float* __restrict__ out,
                            const float* __restrict__ b2, int N) {
    int gw = (blockIdx.x * blockDim.x + threadIdx.x) >> 5;
    int lane = threadIdx.x & 31;
    if (gw >= N) return;
    int d = gw;
    int o = g_off[d];
    int deg = g_off[d + 1] - o;
    float ad = g_ad2[d];

    float m = -INFINITY;
    for (int i = lane; i < deg; i += 32) {
        int s = g_ssrc[o + i];
        m = fmaxf(m, lrelu(g_as2[s] + ad));
    }
#pragma unroll
    for (int off = 16; off >= 1; off >>= 1)
        m = fmaxf(m, __shfl_xor_sync(FULL, m, off));

    float t0 = 0, t1 = 0, den = 0;
    for (int i = lane; i < deg; i += 32) {
        int s = g_ssrc[o + i];
        float w = expf(lrelu(g_as2[s] + ad) - m);
        float2 xv = *(const float2*)&g_xw2[2 * s];
        den += w;
        t0 += w * xv.x;
        t1 += w * xv.y;
    }
#pragma unroll
    for (int off = 16; off >= 1; off >>= 1) {
        t0 += __shfl_xor_sync(FULL, t0, off);
        t1 += __shfl_xor_sync(FULL, t1, off);
        den += __shfl_xor_sync(FULL, den, off);
    }
    if (lane == 0) {
        float invd = 1.0f / (den + 1e-16f);
        out[2 * d]     = t0 * invd + b2[0];
        out[2 * d + 1] = t1 * invd + b2[1];
    }
}

// ---------------------------------------------------------------------------

extern "C" void kernel_launch(void* const* d_in, const int* in_sizes, int n_in,
                              void* d_out, int out_size) {
    const float* x      = (const float*)d_in[0];
    const void*  edges  = d_in[1];
    const float* W1     = (const float*)d_in[2];
    const float* a_src1 = (const float*)d_in[3];
    const float* a_dst1 = (const float*)d_in[4];
    const float* b1     = (const float*)d_in[5];
    const float* W2     = (const float*)d_in[6];
    const float* a_src2 = (const float*)d_in[7];
    const float* a_dst2 = (const float*)d_in[8];
    const float* b2     = (const float*)d_in[9];

    int N = in_sizes[0] / 128;     // 50000
    int E = in_sizes[1] / 2;       // 1600000
    int T = E + N;

    sniff_kernel<<<1, 256>>>((const int*)edges);
    fill_count<<<(N + 255) / 256, 256>>>(N);
    convert_hist<<<(E + 255) / 256, 256>>>(edges, E);
    scan_kernel<<<1, 1024>>>(N);
    scatter_kernel<<<(T + 255) / 256, 256>>>(E, N);

    gemm1_kernel<<<(N + 7) / 8, 128>>>(x, W1, a_src1, a_dst1, N);
    agg1_kernel<<<(N * 32 + 255) / 256, 256>>>(b1, W2, a_src2, a_dst2, N);
    agg2_kernel<<<(N * 32 + 255) / 256, 256>>>((float*)d_out, b2, N);
}

// round 7
// speedup vs baseline: 2.3435x; 1.3064x over previous
#include <cuda_runtime.h>
#include <math.h>
#include <stdint.h>

// ---------------------------------------------------------------------------
// ImbalancedGAT round 4 design (4th submit; broker timeouts): multi-block scan.
//   - convert edges + histogram
//   - 3-pass scan: block sums -> tiny scan of 49 sums -> local scan writing
//     g_off, self-loop slot, and cursor in one sweep
//   - scatter edges only (self loops pre-planted)
//   - gemm1 8 nodes/block; agg1 warp/dst fused (softmax+agg+ELU+GEMM2);
//     agg2 warp/dst -> out
// ---------------------------------------------------------------------------

#define NMAX 50000
#define EMAX 1600000
#define FULL 0xffffffffu
#define SCAN_ELEMS 1024            // elements per scan block
#define SCAN_NB ((NMAX + SCAN_ELEMS - 1) / SCAN_ELEMS)   // 49

__device__ int   g_src[EMAX];
__device__ int   g_dst[EMAX];
__device__ int   g_ssrc[EMAX + NMAX];
__device__ int   g_count[NMAX];
__device__ int   g_off[NMAX + 1];
__device__ int   g_cursor[NMAX];
__device__ int   g_bsum[SCAN_NB];
__device__ int   g_bpre[SCAN_NB];
__device__ float g_xw1[NMAX * 128];
__device__ float g_as1[NMAX * 2];
__device__ float g_ad1[NMAX * 2];
__device__ float g_xw2[NMAX * 2];
__device__ float g_as2[NMAX];
__device__ float g_ad2[NMAX];
__device__ int   g_is64[1];

__device__ __forceinline__ float lrelu(float x) { return x > 0.0f ? x : 0.2f * x; }

// --- dtype sniff ------------------------------------------------------------
__global__ void sniff_kernel(const int* e) {
    __shared__ int any;
    if (threadIdx.x == 0) any = 0;
    __syncthreads();
    if (e[2 * threadIdx.x + 1] != 0) atomicOr(&any, 1);
    __syncthreads();
    if (threadIdx.x == 0) g_is64[0] = (any == 0) ? 1 : 0;
}

__global__ void zero_count(int N) {
    int i = blockIdx.x * blockDim.x + threadIdx.x;
    if (i < N) g_count[i] = 0;
}

// --- convert + histogram ----------------------------------------------------
__global__ void convert_hist(const void* eraw, int E) {
    int i = blockIdx.x * blockDim.x + threadIdx.x;
    if (i >= E) return;
    int s, d;
    if (g_is64[0]) {
        const long long* e = (const long long*)eraw;
        s = (int)e[i];
        d = (int)e[(size_t)E + i];
    } else {
        const int* e = (const int*)eraw;
        s = e[i];
        d = e[E + i];
    }
    g_src[i] = s;
    g_dst[i] = d;
    atomicAdd(&g_count[d], 1);
}

// --- scan pass 1: per-block sums (deg = count+1 incl. self loop) ------------
__global__ void scan_pass1(int N) {
    __shared__ int sh[256];
    int b = blockIdx.x;
    int t = threadIdx.x;
    int base = b * SCAN_ELEMS + t * 4;
    int s = 0;
#pragma unroll
    for (int j = 0; j < 4; j++) {
        int idx = base + j;
        if (idx < N) s += g_count[idx] + 1;
    }
    sh[t] = s;
    __syncthreads();
    for (int off = 128; off >= 1; off >>= 1) {
        if (t < off) sh[t] += sh[t + off];
        __syncthreads();
    }
    if (t == 0) g_bsum[b] = sh[0];
}

// --- scan pass 2: scan SCAN_NB block sums (1 block, 64 threads) -------------
__global__ void scan_pass2(int N) {
    __shared__ int sh[64];
    int t = threadIdx.x;
    int v = (t < SCAN_NB) ? g_bsum[t] : 0;
    sh[t] = v;
    __syncthreads();
    for (int off = 1; off < 64; off <<= 1) {
        int u = (t >= off) ? sh[t - off] : 0;
        __syncthreads();
        sh[t] += u;
        __syncthreads();
    }
    if (t < SCAN_NB) g_bpre[t] = sh[t] - v;   // exclusive
    if (t == 63) g_off[N] = sh[63];
}

// --- scan pass 3: local exclusive scan; write off, self-loop, cursor --------
__global__ void scan_pass3(int N) {
    __shared__ int sh[256];
    int b = blockIdx.x;
    int t = threadIdx.x;
    int base = b * SCAN_ELEMS + t * 4;
    int v[4];
    int s = 0;
#pragma unroll
    for (int j = 0; j < 4; j++) {
        int idx = base + j;
        v[j] = (idx < N) ? (g_count[idx] + 1) : 0;
        s += v[j];
    }
    sh[t] = s;
    __syncthreads();
    for (int off = 1; off < 256; off <<= 1) {
        int u = (t >= off) ? sh[t - off] : 0;
        __syncthreads();
        sh[t] += u;
        __syncthreads();
    }
    int run = g_bpre[b] + sh[t] - s;   // exclusive prefix for this thread
#pragma unroll
    for (int j = 0; j < 4; j++) {
        int idx = base + j;
        if (idx < N) {
            g_off[idx] = run;
            g_ssrc[run] = idx;          // self loop first in segment
            g_cursor[idx] = run + 1;
            run += v[j];
        }
    }
}

// --- counting-sort scatter (edges only) -------------------------------------
__global__ void scatter_kernel(int E) {
    int i = blockIdx.x * blockDim.x + threadIdx.x;
    if (i >= E) return;
    int pos = atomicAdd(&g_cursor[g_dst[i]], 1);
    g_ssrc[pos] = g_src[i];
}

// --- layer 1 GEMM: 8 nodes per block, 128 threads ---------------------------
__global__ void gemm1_kernel(const float* __restrict__ x,
                             const float* __restrict__ W1,
                             const float* __restrict__ a_src1,
                             const float* __restrict__ a_dst1, int N) {
    int nb = blockIdx.x * 8;
    int t = threadIdx.x;
    int lane = t & 31;
    int wid = t >> 5;
    __shared__ float xs[8][128];
    __shared__ float ps[8][4], pd[8][4];
#pragma unroll
    for (int r = 0; r < 8; r++)
        xs[r][t] = x[(nb + r) * 128 + t];
    float a_s = a_src1[t];
    float a_d = a_dst1[t];
    __syncthreads();
    float acc[8] = {0, 0, 0, 0, 0, 0, 0, 0};
    for (int k = 0; k < 128; k += 4) {
        float w0 = W1[(k + 0) * 128 + t];
        float w1 = W1[(k + 1) * 128 + t];
        float w2 = W1[(k + 2) * 128 + t];
        float w3 = W1[(k + 3) * 128 + t];
#pragma unroll
        for (int r = 0; r < 8; r++) {
            float4 xv = *(const float4*)&xs[r][k];
            acc[r] += xv.x * w0 + xv.y * w1 + xv.z * w2 + xv.w * w3;
        }
    }
#pragma unroll
    for (int r = 0; r < 8; r++) {
        g_xw1[(nb + r) * 128 + t] = acc[r];
        float v1 = acc[r] * a_s;
        float v2 = acc[r] * a_d;
#pragma unroll
        for (int o = 16; o >= 1; o >>= 1) {
            v1 += __shfl_down_sync(FULL, v1, o);
            v2 += __shfl_down_sync(FULL, v2, o);
        }
        if (lane == 0) { ps[r][wid] = v1; pd[r][wid] = v2; }
    }
    __syncthreads();
    if (t < 8) {
        int n = nb + t;
        g_as1[2 * n]     = ps[t][0] + ps[t][1];
        g_as1[2 * n + 1] = ps[t][2] + ps[t][3];
        g_ad1[2 * n]     = pd[t][0] + pd[t][1];
        g_ad1[2 * n + 1] = pd[t][2] + pd[t][3];
    }
}

// --- layer 1 aggregate: warp per dst node, fused everything -----------------
__global__ void agg1_kernel(const float* __restrict__ b1,
                            const float* __restrict__ W2,
                            const float* __restrict__ a_src2,
                            const float* __restrict__ a_dst2, int N) {
    int gw = (blockIdx.x * blockDim.x + threadIdx.x) >> 5;
    int lane = threadIdx.x & 31;
    if (gw >= N) return;
    int d = gw;
    int o = g_off[d];
    int deg = g_off[d + 1] - o;
    float ad0 = g_ad1[2 * d];
    float ad1 = g_ad1[2 * d + 1];

    // phase 1: per-head max logit
    float m0 = -INFINITY, m1 = -INFINITY;
    for (int i = lane; i < deg; i += 32) {
        int s = g_ssrc[o + i];
        float2 as = *(const float2*)&g_as1[2 * s];
        m0 = fmaxf(m0, lrelu(as.x + ad0));
        m1 = fmaxf(m1, lrelu(as.y + ad1));
    }
#pragma unroll
    for (int off = 16; off >= 1; off >>= 1) {
        m0 = fmaxf(m0, __shfl_xor_sync(FULL, m0, off));
        m1 = fmaxf(m1, __shfl_xor_sync(FULL, m1, off));
    }

    // phase 2: weighted aggregation; lane owns channels [4*lane, 4*lane+4)
    int head = lane >> 4;
    float acc0 = 0, acc1 = 0, acc2 = 0, acc3 = 0;
    float den0 = 0, den1 = 0;
    int base = 0;
    for (; base + 32 <= deg; base += 32) {
        int s = g_ssrc[o + base + lane];
        float2 as = *(const float2*)&g_as1[2 * s];
        float w0 = expf(lrelu(as.x + ad0) - m0);
        float w1 = expf(lrelu(as.y + ad1) - m1);
        den0 += w0;
        den1 += w1;
#pragma unroll 8
        for (int j = 0; j < 32; j++) {
            int sj = __shfl_sync(FULL, s, j);
            float wa = __shfl_sync(FULL, w0, j);
            float wb = __shfl_sync(FULL, w1, j);
            float wj = head ? wb : wa;
            float4 xv = *(const float4*)&g_xw1[sj * 128 + lane * 4];
            acc0 += wj * xv.x;
            acc1 += wj * xv.y;
            acc2 += wj * xv.z;
            acc3 += wj * xv.w;
        }
    }
    int rem = deg - base;
    if (rem > 0) {
        int s = 0;
        float w0 = 0, w1 = 0;
        if (lane < rem) {
            s = g_ssrc[o + base + lane];
            float2 as = *(const float2*)&g_as1[2 * s];
            w0 = expf(lrelu(as.x + ad0) - m0);
            w1 = expf(lrelu(as.y + ad1) - m1);
            den0 += w0;
            den1 += w1;
        }
        for (int j = 0; j < rem; j++) {
            int sj = __shfl_sync(FULL, s, j);
            float wa = __shfl_sync(FULL, w0, j);
            float wb = __shfl_sync(FULL, w1, j);
            float wj = head ? wb : wa;
            float4 xv = *(const float4*)&g_xw1[sj * 128 + lane * 4];
            acc0 += wj * xv.x;
            acc1 += wj * xv.y;
            acc2 += wj * xv.z;
            acc3 += wj * xv.w;
        }
    }
#pragma unroll
    for (int off = 16; off >= 1; off >>= 1) {
        den0 += __shfl_xor_sync(FULL, den0, off);
        den1 += __shfl_xor_sync(FULL, den1, off);
    }
    float inv = 1.0f / ((head ? den1 : den0) + 1e-16f);

    int c = lane * 4;
    float h0 = acc0 * inv + b1[c + 0];
    float h1 = acc1 * inv + b1[c + 1];
    float h2 = acc2 * inv + b1[c + 2];
    float h3 = acc3 * inv + b1[c + 3];
    h0 = h0 > 0.0f ? h0 : expm1f(h0);
    h1 = h1 > 0.0f ? h1 : expm1f(h1);
    h2 = h2 > 0.0f ? h2 : expm1f(h2);
    h3 = h3 > 0.0f ? h3 : expm1f(h3);

    float s0 = h0 * W2[2 * c + 0] + h1 * W2[2 * c + 2] + h2 * W2[2 * c + 4] + h3 * W2[2 * c + 6];
    float s1 = h0 * W2[2 * c + 1] + h1 * W2[2 * c + 3] + h2 * W2[2 * c + 5] + h3 * W2[2 * c + 7];
#pragma unroll
    for (int off = 16; off >= 1; off >>= 1) {
        s0 += __shfl_xor_sync(FULL, s0, off);
        s1 += __shfl_xor_sync(FULL, s1, off);
    }
    if (lane == 0) {
        g_xw2[2 * d]     = s0;
        g_xw2[2 * d + 1] = s1;
        g_as2[d] = s0 * a_src2[0] + s1 * a_src2[1];
        g_ad2[d] = s0 * a_dst2[0] + s1 * a_dst2[1];
    }
}

// --- layer 2 aggregate: warp per dst node, writes output --------------------
__global__ void agg2_kernel(float* __restrict__ out,
                            const float* __restrict__ b2, int N) {
    int gw = (blockIdx.x * blockDim.x + threadIdx.x) >> 5;
    int lane = threadIdx.x & 31;
    if (gw >= N) return;
    int d = gw;
    int o = g_off[d];
    int deg = g_off[d + 1] - o;
    float ad = g_ad2[d];

    float m = -INFINITY;
    for (int i = lane; i < deg; i += 32) {
        int s = g_ssrc[o + i];
        m = fmaxf(m, lrelu(g_as2[s] + ad));
    }
#pragma unroll
    for (int off = 16; off >= 1; off >>= 1)
        m = fmaxf(m, __shfl_xor_sync(FULL, m, off));

    float t0 = 0, t1 = 0, den = 0;
    for (int i = lane; i < deg; i += 32) {
        int s = g_ssrc[o + i];
        float w = expf(lrelu(g_as2[s] + ad) - m);
        float2 xv = *(const float2*)&g_xw2[2 * s];
        den += w;
        t0 += w * xv.x;
        t1 += w * xv.y;
    }
#pragma unroll
    for (int off = 16; off >= 1; off >>= 1) {
        t0 += __shfl_xor_sync(FULL, t0, off);
        t1 += __shfl_xor_sync(FULL, t1, off);
        den += __shfl_xor_sync(FULL, den, off);
    }
    if (lane == 0) {
        float invd = 1.0f / (den + 1e-16f);
        out[2 * d]     = t0 * invd + b2[0];
        out[2 * d + 1] = t1 * invd + b2[1];
    }
}

// ---------------------------------------------------------------------------

extern "C" void kernel_launch(void* const* d_in, const int* in_sizes, int n_in,
                              void* d_out, int out_size) {
    const float* x      = (const float*)d_in[0];
    const void*  edges  = d_in[1];
    const float* W1     = (const float*)d_in[2];
    const float* a_src1 = (const float*)d_in[3];
    const float* a_dst1 = (const float*)d_in[4];
    const float* b1     = (const float*)d_in[5];
    const float* W2     = (const float*)d_in[6];
    const float* a_src2 = (const float*)d_in[7];
    const float* a_dst2 = (const float*)d_in[8];
    const float* b2     = (const float*)d_in[9];

    int N = in_sizes[0] / 128;     // 50000
    int E = in_sizes[1] / 2;       // 1600000

    sniff_kernel<<<1, 256>>>((const int*)edges);
    zero_count<<<(N + 255) / 256, 256>>>(N);
    convert_hist<<<(E + 255) / 256, 256>>>(edges, E);
    scan_pass1<<<SCAN_NB, 256>>>(N);
    scan_pass2<<<1, 64>>>(N);
    scan_pass3<<<SCAN_NB, 256>>>(N);
    scatter_kernel<<<(E + 255) / 256, 256>>>(E);

    gemm1_kernel<<<(N + 7) / 8, 128>>>(x, W1, a_src1, a_dst1, N);
    agg1_kernel<<<(N * 32 + 255) / 256, 256>>>(b1, W2, a_src2, a_dst2, N);
    agg2_kernel<<<(N * 32 + 255) / 256, 256>>>((float*)d_out, b2, N);
}